// round 1
// baseline (speedup 1.0000x reference)
#include <cuda_runtime.h>
#include <cuda_bf16.h>

// Problem constants
#define B_SZ   4096
#define DIN    768
#define DOUT   512
#define Q_SZ   64
#define H1_SZ  32
#define H2_SZ  64
#define EPS    1e-5f

// Scratch for x_proj = x @ wp + bp  (8 MB, static __device__ per harness rules)
__device__ float g_xproj[B_SZ * DOUT];

// ---------------------------------------------------------------------------
// Kernel 1: SGEMM  C[M,N] = A[M,K] @ B[K,N] + bias[N]
// M=4096, N=512, K=768.  128x128 block tile, BK=16, 8x8 thread tile, 256 thr.
// ---------------------------------------------------------------------------
#define BM 128
#define BN 128
#define BK 16
#define TM 8
#define TN 8

__global__ void __launch_bounds__(256, 2)
sgemm_bias(const float* __restrict__ A, const float* __restrict__ Bm,
           const float* __restrict__ bias, float* __restrict__ C)
{
    const int M = B_SZ, N = DOUT, K = DIN;
    __shared__ float As[BK][BM];   // transposed A tile
    __shared__ float Bs[BK][BN];

    const int tid = threadIdx.x;
    const int bm  = blockIdx.y;
    const int bn  = blockIdx.x;

    const float* Ab = A  + (long)bm * BM * K;
    const float* Bb = Bm + (long)bn * BN;

    // A tile load: 128 rows x 16 cols = 512 float4; thread -> (row, 4-col)
    const int aRow = tid >> 2;           // 0..63  (two rows per thread, +64)
    const int aCol = (tid & 3) * 4;      // 0,4,8,12
    // B tile load: 16 rows x 128 cols = 512 float4
    const int bRow = tid >> 5;           // 0..7  (two rows per thread, +8)
    const int bCol = (tid & 31) * 4;

    const int tRow = (tid >> 4) * TM;    // 0..120
    const int tCol = (tid & 15) * TN;

    float acc[TM][TN];
    #pragma unroll
    for (int i = 0; i < TM; i++)
        #pragma unroll
        for (int j = 0; j < TN; j++) acc[i][j] = 0.f;

    for (int k0 = 0; k0 < K; k0 += BK) {
        #pragma unroll
        for (int i = 0; i < 2; i++) {
            const int r = aRow + i * 64;
            float4 v = *(const float4*)(Ab + (long)r * K + k0 + aCol);
            As[aCol + 0][r] = v.x;
            As[aCol + 1][r] = v.y;
            As[aCol + 2][r] = v.z;
            As[aCol + 3][r] = v.w;
        }
        #pragma unroll
        for (int i = 0; i < 2; i++) {
            const int r = bRow + i * 8;
            float4 v = *(const float4*)(Bb + (long)(k0 + r) * N + bCol);
            *(float4*)(&Bs[r][bCol]) = v;
        }
        __syncthreads();

        #pragma unroll
        for (int k = 0; k < BK; k++) {
            float ra[TM], rb[TN];
            #pragma unroll
            for (int i = 0; i < TM; i++) ra[i] = As[k][tRow + i];
            #pragma unroll
            for (int j = 0; j < TN; j++) rb[j] = Bs[k][tCol + j];
            #pragma unroll
            for (int i = 0; i < TM; i++)
                #pragma unroll
                for (int j = 0; j < TN; j++)
                    acc[i][j] = fmaf(ra[i], rb[j], acc[i][j]);
        }
        __syncthreads();
    }

    // Epilogue: add bias, store
    #pragma unroll
    for (int i = 0; i < TM; i++) {
        const long row = (long)bm * BM + tRow + i;
        #pragma unroll
        for (int j = 0; j < TN; j += 4) {
            const int col = bn * BN + tCol + j;
            float4 o;
            o.x = acc[i][j + 0] + bias[col + 0];
            o.y = acc[i][j + 1] + bias[col + 1];
            o.z = acc[i][j + 2] + bias[col + 2];
            o.w = acc[i][j + 3] + bias[col + 3];
            *(float4*)(&C[row * N + col]) = o;
        }
    }
}

// ---------------------------------------------------------------------------
// Kernel 2: fused  S -> u -> G -> (G@wo2 + Q*bo2) -> LayerNorm
// 8 batch-rows per block, 256 threads.
// ---------------------------------------------------------------------------
#define ROWS 8

__global__ void __launch_bounds__(256)
kan_fused(const float* __restrict__ xproj,
          const float* __restrict__ wi1, const float* __restrict__ bi1,
          const float* __restrict__ wi2, const float* __restrict__ bi2,
          const float* __restrict__ wo1, const float* __restrict__ bo1,
          const float* __restrict__ wo2, const float* __restrict__ bo2,
          const float* __restrict__ gamma, const float* __restrict__ beta,
          float* __restrict__ out)
{
    __shared__ float rows[ROWS][DOUT];      // 16 KB
    __shared__ float Ssh[ROWS][H1_SZ];
    __shared__ float ush[ROWS][Q_SZ];
    __shared__ float Gsh[ROWS][H2_SZ];
    __shared__ float red[ROWS][8][2];       // per-warp (sum, sumsq)

    const int tid  = threadIdx.x;
    const int warp = tid >> 5;
    const int lane = tid & 31;
    const long base = (long)blockIdx.x * ROWS * DOUT;

    // Load 8 rows of x_proj (4096 floats) coalesced as float4
    {
        const float4* src = (const float4*)(xproj + base);
        float4* dst = (float4*)(&rows[0][0]);
        #pragma unroll
        for (int i = 0; i < 4; i++) dst[tid + i * 256] = src[tid + i * 256];
    }
    __syncthreads();

    // Stage B: S[r][h] = sum_d relu(v*wi1[h]+bi1[h]); warp=row, lane=h (H1=32)
    {
        const float w1 = wi1[lane];
        const float b1 = bi1[lane];
        float s = 0.f;
        #pragma unroll 8
        for (int d = 0; d < DOUT; d++) {
            const float v = rows[warp][d];               // LDS broadcast
            s += fmaxf(fmaf(v, w1, b1), 0.f);
        }
        Ssh[warp][lane] = s;
    }
    __syncthreads();

    // Stage C: u[r][q] = sum_h S[r][h]*wi2[h][q] + DOUT*bi2[q]
    #pragma unroll
    for (int it = 0; it < 2; it++) {
        const int idx = tid + it * 256;
        const int r = idx >> 6, q = idx & 63;
        float acc = (float)DOUT * bi2[q];
        #pragma unroll
        for (int h = 0; h < H1_SZ; h++)
            acc = fmaf(Ssh[r][h], wi2[h * Q_SZ + q], acc);
        ush[r][q] = acc;
    }
    __syncthreads();

    // Stage D: G[r][h2] = sum_q relu(u[r][q]*wo1[h2]+bo1[h2])
    #pragma unroll
    for (int it = 0; it < 2; it++) {
        const int idx = tid + it * 256;
        const int r = idx >> 6, h2 = idx & 63;
        const float w = wo1[h2];
        const float b = bo1[h2];
        float g = 0.f;
        #pragma unroll
        for (int q = 0; q < Q_SZ; q++)
            g += fmaxf(fmaf(ush[r][q], w, b), 0.f);
        Gsh[r][h2] = g;
    }
    __syncthreads();

    // Stage E: summed[r][d] = sum_h2 G[r][h2]*wo2[h2][d] + Q*bo2[d]
    const int d0 = tid;
    const int d1 = tid + 256;
    float acc0[ROWS], acc1[ROWS];
    #pragma unroll
    for (int r = 0; r < ROWS; r++) { acc0[r] = 0.f; acc1[r] = 0.f; }

    #pragma unroll 4
    for (int h2 = 0; h2 < H2_SZ; h2++) {
        const float w0 = wo2[h2 * DOUT + d0];            // coalesced, L2-resident
        const float w1v = wo2[h2 * DOUT + d1];
        #pragma unroll
        for (int r = 0; r < ROWS; r++) {
            const float g = Gsh[r][h2];                  // LDS broadcast
            acc0[r] = fmaf(g, w0, acc0[r]);
            acc1[r] = fmaf(g, w1v, acc1[r]);
        }
    }
    {
        const float bb0 = (float)Q_SZ * bo2[d0];
        const float bb1 = (float)Q_SZ * bo2[d1];
        #pragma unroll
        for (int r = 0; r < ROWS; r++) { acc0[r] += bb0; acc1[r] += bb1; }
    }

    // LayerNorm reductions: warp shuffle then cross-warp via shared
    #pragma unroll
    for (int r = 0; r < ROWS; r++) {
        float ps = acc0[r] + acc1[r];
        float pq = acc0[r] * acc0[r] + acc1[r] * acc1[r];
        #pragma unroll
        for (int off = 16; off > 0; off >>= 1) {
            ps += __shfl_xor_sync(0xffffffffu, ps, off);
            pq += __shfl_xor_sync(0xffffffffu, pq, off);
        }
        if (lane == 0) { red[r][warp][0] = ps; red[r][warp][1] = pq; }
    }
    __syncthreads();

    const float g0 = gamma[d0], g1 = gamma[d1];
    const float be0 = beta[d0], be1 = beta[d1];
    #pragma unroll
    for (int r = 0; r < ROWS; r++) {
        float s = 0.f, q2 = 0.f;
        #pragma unroll
        for (int w = 0; w < 8; w++) { s += red[r][w][0]; q2 += red[r][w][1]; }
        const float mu  = s * (1.f / (float)DOUT);
        const float var = q2 * (1.f / (float)DOUT) - mu * mu;
        const float inv = rsqrtf(var + EPS);
        const long ob = base + (long)r * DOUT;
        out[ob + d0] = (acc0[r] - mu) * inv * g0 + be0;
        out[ob + d1] = (acc1[r] - mu) * inv * g1 + be1;
    }
}

// ---------------------------------------------------------------------------
// Launch
// ---------------------------------------------------------------------------
extern "C" void kernel_launch(void* const* d_in, const int* in_sizes, int n_in,
                              void* d_out, int out_size)
{
    const float* x     = (const float*)d_in[0];
    const float* wp    = (const float*)d_in[1];
    const float* bp    = (const float*)d_in[2];
    const float* wi1   = (const float*)d_in[3];
    const float* bi1   = (const float*)d_in[4];
    const float* wi2   = (const float*)d_in[5];
    const float* bi2   = (const float*)d_in[6];
    const float* wo1   = (const float*)d_in[7];
    const float* bo1   = (const float*)d_in[8];
    const float* wo2   = (const float*)d_in[9];
    const float* bo2   = (const float*)d_in[10];
    const float* gamma = (const float*)d_in[11];
    const float* beta  = (const float*)d_in[12];
    float* out = (float*)d_out;

    float* xproj;
    cudaGetSymbolAddress((void**)&xproj, g_xproj);

    dim3 g1(DOUT / BN, B_SZ / BM);        // (4, 32)
    sgemm_bias<<<g1, 256>>>(x, wp, bp, xproj);

    kan_fused<<<B_SZ / ROWS, 256>>>(xproj, wi1, bi1, wi2, bi2,
                                    wo1, bo1, wo2, bo2, gamma, beta, out);
}

// round 3
// speedup vs baseline: 1.8145x; 1.8145x over previous
#include <cuda_runtime.h>
#include <cuda_bf16.h>
#include <cstdint>

// Problem constants
#define B_SZ   4096
#define DIN    768
#define DOUT   512
#define Q_SZ   64
#define H1_SZ  32
#define H2_SZ  64
#define EPS    1e-5f

// Split-K for bf16 3-term compensated GEMM: K' = 3 * DIN
#define KSPLIT (3 * DIN)        // 2304
#define KC     64               // K per chunk (bf16), 128 bytes/row -> SW128 layout
#define NCH    (KSPLIT / KC)    // 36
#define GS     4                // pipeline stages
#define TILEB  16384            // one 128x64 bf16 tile
#define STAGEB (2 * TILEB)      // A + B tile per stage

// ---------------------------------------------------------------------------
// Static device scratch (no allocations allowed)
// ---------------------------------------------------------------------------
__device__ __align__(256) float          g_xproj[B_SZ * DOUT];          // 8 MB
__device__ __align__(256) __nv_bfloat16  g_A[B_SZ * KSPLIT];            // 18.9 MB
__device__ __align__(256) __nv_bfloat16  g_Bt[DOUT * KSPLIT];           // 2.36 MB

// ---------------------------------------------------------------------------
// Helpers
// ---------------------------------------------------------------------------
__device__ __forceinline__ uint32_t smem_u32(const void* p) {
    uint32_t a;
    asm("{ .reg .u64 t; cvta.to.shared.u64 t, %1; cvt.u32.u64 %0, t; }"
        : "=r"(a) : "l"(p));
    return a;
}

__device__ __forceinline__ uint32_t swz(uint32_t off) {
    return off ^ ((off >> 3) & 0x70);           // SW128: bits[6:4] ^= bits[9:7]
}

__device__ __forceinline__ void cpasync16(uint32_t dst, const void* src) {
    asm volatile("cp.async.cg.shared.global [%0], [%1], 16;"
                 :: "r"(dst), "l"(src) : "memory");
}

__device__ __forceinline__ void ldsm_x4(uint32_t* r, uint32_t addr) {
    asm volatile("ldmatrix.sync.aligned.m8n8.x4.shared.b16 {%0,%1,%2,%3}, [%4];"
                 : "=r"(r[0]), "=r"(r[1]), "=r"(r[2]), "=r"(r[3]) : "r"(addr));
}
__device__ __forceinline__ void ldsm_x2(uint32_t* r, uint32_t addr) {
    asm volatile("ldmatrix.sync.aligned.m8n8.x2.shared.b16 {%0,%1}, [%2];"
                 : "=r"(r[0]), "=r"(r[1]) : "r"(addr));
}

__device__ __forceinline__ void mma16816(float* d, const uint32_t* a, const uint32_t* b) {
    asm volatile(
        "mma.sync.aligned.m16n8k16.row.col.f32.bf16.bf16.f32 "
        "{%0,%1,%2,%3}, {%4,%5,%6,%7}, {%8,%9}, {%0,%1,%2,%3};"
        : "+f"(d[0]), "+f"(d[1]), "+f"(d[2]), "+f"(d[3])
        : "r"(a[0]), "r"(a[1]), "r"(a[2]), "r"(a[3]), "r"(b[0]), "r"(b[1]));
}

// ---------------------------------------------------------------------------
// Conversion kernels: fp32 -> bf16 hi/lo split, folded into K
// A'[m, 0:768)=hi(x), [768:1536)=hi(x), [1536:2304)=lo(x)
// B'[n, 0:768)=hi(w^T), [768:1536)=lo(w^T), [1536:2304)=hi(w^T)
// => A'@B'^T = hi@hi + hi@lo + lo@hi  ~= x @ w  (error ~2^-18 per term)
// ---------------------------------------------------------------------------
__global__ void __launch_bounds__(256)
conv_x(const float* __restrict__ x, __nv_bfloat16* __restrict__ A)
{
    const int row = blockIdx.x;
    const float* xr = x + (long)row * DIN;
    __nv_bfloat16* Ar = A + (long)row * KSPLIT;
    #pragma unroll
    for (int i = 0; i < 3; i++) {
        const int k = threadIdx.x + i * 256;
        const float v = xr[k];
        const __nv_bfloat16 hi = __float2bfloat16(v);
        const __nv_bfloat16 lo = __float2bfloat16(v - __bfloat162float(hi));
        Ar[k]            = hi;
        Ar[k + DIN]      = hi;
        Ar[k + 2 * DIN]  = lo;
    }
}

__global__ void __launch_bounds__(256)
conv_w(const float* __restrict__ wp, __nv_bfloat16* __restrict__ Bt)
{
    __shared__ float t[32][33];
    const int k0 = blockIdx.x * 32, n0 = blockIdx.y * 32;
    const int tx = threadIdx.x & 31;
    const int ty = threadIdx.x >> 5;
    #pragma unroll
    for (int dy = 0; dy < 32; dy += 8)
        t[ty + dy][tx] = wp[(long)(k0 + ty + dy) * DOUT + n0 + tx];
    __syncthreads();
    #pragma unroll
    for (int dy = 0; dy < 32; dy += 8) {
        const int n = n0 + ty + dy, k = k0 + tx;
        const float v = t[tx][ty + dy];
        const __nv_bfloat16 hi = __float2bfloat16(v);
        const __nv_bfloat16 lo = __float2bfloat16(v - __bfloat162float(hi));
        __nv_bfloat16* Br = Bt + (long)n * KSPLIT;
        Br[k]           = hi;
        Br[k + DIN]     = lo;
        Br[k + 2 * DIN] = hi;
    }
}

// ---------------------------------------------------------------------------
// mma.sync bf16 GEMM: C[4096,512] = A'[4096,2304] @ B'^T  (B' stored [512,2304])
// 128x128 CTA tile, 8 warps (2m x 4n), 64x32 per warp. KC=64 chunks,
// 4-stage cp.async pipeline. HMMA.16816 path (tcgen05 unavailable: the harness
// lowers through compute_103 PTX, which rejects tcgen05).
// ---------------------------------------------------------------------------
__global__ void __launch_bounds__(256, 1)
gemm_tc(const __nv_bfloat16* __restrict__ Ag, const __nv_bfloat16* __restrict__ Bg,
        const float* __restrict__ bias, float* __restrict__ C)
{
    extern __shared__ char dynsmem[];

    const int tid  = threadIdx.x;
    const int warp = tid >> 5, lane = tid & 31;
    const int wm = warp >> 2;                 // 0..1
    const int wn = warp & 3;                  // 0..3
    const int bn = blockIdx.x, bm = blockIdx.y;

    const uint32_t abase = (smem_u32(dynsmem) + 1023u) & ~1023u;

    const __nv_bfloat16* Atile = Ag + (long)(bm * 128) * KSPLIT;
    const __nv_bfloat16* Btile = Bg + (long)(bn * 128) * KSPLIT;

    // chunk loader: 128 rows x 64 bf16 (128B rows, SW128-swizzled) per matrix
    auto load_chunk = [&](int c, int s) {
        const uint32_t sa = abase + s * STAGEB;
        const uint32_t sb = sa + TILEB;
        const int koff = c * KC;
        #pragma unroll
        for (int it = 0; it < 4; it++) {
            const int idx = it * 256 + tid;            // 0..1023
            const int row = idx >> 3;
            const int c16 = idx & 7;
            const uint32_t soff = swz(row * 128 + c16 * 16);
            cpasync16(sa + soff, Atile + (long)row * KSPLIT + koff + c16 * 8);
            cpasync16(sb + soff, Btile + (long)row * KSPLIT + koff + c16 * 8);
        }
        asm volatile("cp.async.commit_group;" ::: "memory");
    };

    float acc[4][4][4];
    #pragma unroll
    for (int mt = 0; mt < 4; mt++)
        #pragma unroll
        for (int nt = 0; nt < 4; nt++)
            #pragma unroll
            for (int j = 0; j < 4; j++) acc[mt][nt][j] = 0.f;

    // precompute per-lane ldmatrix smem offsets (within a stage)
    const uint32_t a_row = wm * 64 + (lane & 15);
    const uint32_t a_seg = (lane >> 4) * 16;
    const uint32_t b_row = wn * 32 + (lane & 7);
    const uint32_t b_seg = ((lane >> 3) & 1) * 16;

    // prologue: 3 chunks in flight
    #pragma unroll
    for (int c = 0; c < GS - 1; c++) load_chunk(c, c);

    for (int c = 0; c < NCH; c++) {
        asm volatile("cp.async.wait_group %0;" :: "n"(GS - 2) : "memory");
        __syncthreads();

        const int nl = c + GS - 1;
        if (nl < NCH) load_chunk(nl, nl & (GS - 1));

        const uint32_t sa = abase + (c & (GS - 1)) * STAGEB;
        const uint32_t sb = sa + TILEB;

        #pragma unroll
        for (int ks = 0; ks < 4; ks++) {
            uint32_t af[4][4], bf[4][2];
            #pragma unroll
            for (int mt = 0; mt < 4; mt++)
                ldsm_x4(af[mt], sa + swz((a_row + mt * 16) * 128 + ks * 32 + a_seg));
            #pragma unroll
            for (int nt = 0; nt < 4; nt++)
                ldsm_x2(bf[nt], sb + swz((b_row + nt * 8) * 128 + ks * 32 + b_seg));
            #pragma unroll
            for (int mt = 0; mt < 4; mt++)
                #pragma unroll
                for (int nt = 0; nt < 4; nt++)
                    mma16816(acc[mt][nt], af[mt], bf[nt]);
        }
    }

    // epilogue: +bias, store. C frag: lane -> (row l/4, col 2*(l%4)), rows +8.
    const int g  = lane >> 2;
    const int tg = lane & 3;
    #pragma unroll
    for (int mt = 0; mt < 4; mt++) {
        const int m = bm * 128 + wm * 64 + mt * 16 + g;
        #pragma unroll
        for (int nt = 0; nt < 4; nt++) {
            const int n = bn * 128 + wn * 32 + nt * 8 + 2 * tg;
            const float b0 = bias[n], b1 = bias[n + 1];
            float2 v0, v1;
            v0.x = acc[mt][nt][0] + b0;  v0.y = acc[mt][nt][1] + b1;
            v1.x = acc[mt][nt][2] + b0;  v1.y = acc[mt][nt][3] + b1;
            *(float2*)(C + (long)m * DOUT + n)       = v0;
            *(float2*)(C + (long)(m + 8) * DOUT + n) = v1;
        }
    }
}

// ---------------------------------------------------------------------------
// Kernel 2: fused  S -> u -> G -> (G@wo2 + Q*bo2) -> LayerNorm
// ---------------------------------------------------------------------------
#define ROWS 8

__global__ void __launch_bounds__(256)
kan_fused(const float* __restrict__ xproj,
          const float* __restrict__ wi1, const float* __restrict__ bi1,
          const float* __restrict__ wi2, const float* __restrict__ bi2,
          const float* __restrict__ wo1, const float* __restrict__ bo1,
          const float* __restrict__ wo2, const float* __restrict__ bo2,
          const float* __restrict__ gamma, const float* __restrict__ beta,
          float* __restrict__ out)
{
    __shared__ float rows[ROWS][DOUT];
    __shared__ float Ssh[ROWS][H1_SZ];
    __shared__ float ush[ROWS][Q_SZ];
    __shared__ float Gsh[ROWS][H2_SZ];
    __shared__ float red[ROWS][8][2];

    const int tid  = threadIdx.x;
    const int warp = tid >> 5;
    const int lane = tid & 31;
    const long base = (long)blockIdx.x * ROWS * DOUT;

    {
        const float4* src = (const float4*)(xproj + base);
        float4* dst = (float4*)(&rows[0][0]);
        #pragma unroll
        for (int i = 0; i < 4; i++) dst[tid + i * 256] = src[tid + i * 256];
    }
    __syncthreads();

    // Stage B: S[r][h] = sum_d relu(v*wi1[h]+bi1[h]); warp=row, lane=h, float4 LDS
    {
        const float w1 = wi1[lane];
        const float b1 = bi1[lane];
        float s0 = 0.f, s1 = 0.f, s2 = 0.f, s3 = 0.f;
        const float4* rv = (const float4*)(&rows[warp][0]);
        #pragma unroll 4
        for (int d4 = 0; d4 < DOUT / 4; d4++) {
            const float4 v = rv[d4];                  // LDS.128 broadcast
            s0 += fmaxf(fmaf(v.x, w1, b1), 0.f);
            s1 += fmaxf(fmaf(v.y, w1, b1), 0.f);
            s2 += fmaxf(fmaf(v.z, w1, b1), 0.f);
            s3 += fmaxf(fmaf(v.w, w1, b1), 0.f);
        }
        Ssh[warp][lane] = (s0 + s1) + (s2 + s3);
    }
    __syncthreads();

    #pragma unroll
    for (int it = 0; it < 2; it++) {
        const int idx = tid + it * 256;
        const int r = idx >> 6, q = idx & 63;
        float acc = (float)DOUT * bi2[q];
        #pragma unroll
        for (int h = 0; h < H1_SZ; h++)
            acc = fmaf(Ssh[r][h], wi2[h * Q_SZ + q], acc);
        ush[r][q] = acc;
    }
    __syncthreads();

    #pragma unroll
    for (int it = 0; it < 2; it++) {
        const int idx = tid + it * 256;
        const int r = idx >> 6, h2 = idx & 63;
        const float w = wo1[h2];
        const float b = bo1[h2];
        float g = 0.f;
        #pragma unroll
        for (int q = 0; q < Q_SZ; q++)
            g += fmaxf(fmaf(ush[r][q], w, b), 0.f);
        Gsh[r][h2] = g;
    }
    __syncthreads();

    const int d0 = tid;
    const int d1 = tid + 256;
    float acc0[ROWS], acc1[ROWS];
    #pragma unroll
    for (int r = 0; r < ROWS; r++) { acc0[r] = 0.f; acc1[r] = 0.f; }

    #pragma unroll 4
    for (int h2 = 0; h2 < H2_SZ; h2++) {
        const float w0  = wo2[h2 * DOUT + d0];
        const float w1v = wo2[h2 * DOUT + d1];
        #pragma unroll
        for (int r = 0; r < ROWS; r++) {
            const float g = Gsh[r][h2];
            acc0[r] = fmaf(g, w0, acc0[r]);
            acc1[r] = fmaf(g, w1v, acc1[r]);
        }
    }
    {
        const float bb0 = (float)Q_SZ * bo2[d0];
        const float bb1 = (float)Q_SZ * bo2[d1];
        #pragma unroll
        for (int r = 0; r < ROWS; r++) { acc0[r] += bb0; acc1[r] += bb1; }
    }

    #pragma unroll
    for (int r = 0; r < ROWS; r++) {
        float ps = acc0[r] + acc1[r];
        float pq = acc0[r] * acc0[r] + acc1[r] * acc1[r];
        #pragma unroll
        for (int off = 16; off > 0; off >>= 1) {
            ps += __shfl_xor_sync(0xffffffffu, ps, off);
            pq += __shfl_xor_sync(0xffffffffu, pq, off);
        }
        if (lane == 0) { red[r][warp][0] = ps; red[r][warp][1] = pq; }
    }
    __syncthreads();

    const float g0 = gamma[d0], g1 = gamma[d1];
    const float be0 = beta[d0], be1 = beta[d1];
    #pragma unroll
    for (int r = 0; r < ROWS; r++) {
        float s = 0.f, q2 = 0.f;
        #pragma unroll
        for (int w = 0; w < 8; w++) { s += red[r][w][0]; q2 += red[r][w][1]; }
        const float mu  = s * (1.f / (float)DOUT);
        const float var = q2 * (1.f / (float)DOUT) - mu * mu;
        const float inv = rsqrtf(var + EPS);
        const long ob = base + (long)r * DOUT;
        out[ob + d0] = (acc0[r] - mu) * inv * g0 + be0;
        out[ob + d1] = (acc1[r] - mu) * inv * g1 + be1;
    }
}

// ---------------------------------------------------------------------------
// Launch
// ---------------------------------------------------------------------------
extern "C" void kernel_launch(void* const* d_in, const int* in_sizes, int n_in,
                              void* d_out, int out_size)
{
    const float* x     = (const float*)d_in[0];
    const float* wp    = (const float*)d_in[1];
    const float* bp    = (const float*)d_in[2];
    const float* wi1   = (const float*)d_in[3];
    const float* bi1   = (const float*)d_in[4];
    const float* wi2   = (const float*)d_in[5];
    const float* bi2   = (const float*)d_in[6];
    const float* wo1   = (const float*)d_in[7];
    const float* bo1   = (const float*)d_in[8];
    const float* wo2   = (const float*)d_in[9];
    const float* bo2   = (const float*)d_in[10];
    const float* gamma = (const float*)d_in[11];
    const float* beta  = (const float*)d_in[12];
    float* out = (float*)d_out;

    float* xproj;          cudaGetSymbolAddress((void**)&xproj, g_xproj);
    __nv_bfloat16* Ab;     cudaGetSymbolAddress((void**)&Ab, g_A);
    __nv_bfloat16* Bb;     cudaGetSymbolAddress((void**)&Bb, g_Bt);

    conv_x<<<B_SZ, 256>>>(x, Ab);
    conv_w<<<dim3(DIN / 32, DOUT / 32), 256>>>(wp, Bb);

    const int dyn = GS * STAGEB + 1024;   // 132 KB
    cudaFuncSetAttribute(gemm_tc, cudaFuncAttributeMaxDynamicSharedMemorySize, dyn);
    gemm_tc<<<dim3(DOUT / 128, B_SZ / 128), 256, dyn>>>(Ab, Bb, bp, xproj);

    kan_fused<<<B_SZ / ROWS, 256>>>(xproj, wi1, bi1, wi2, bi2,
                                    wo1, bo1, wo2, bo2, gamma, beta, out);
}